// round 3
// baseline (speedup 1.0000x reference)
#include <cuda_runtime.h>
#include <math.h>

#define BB 8
#define NN 2048
#define FF 64
#define ALPHA_ 0.2f
#define SEG 64
#define NSEG (NN/SEG)     // 32
#define STR 132           // channel stride: 64 + 64 + 2 scalar + pad

// ---- scratch (static device globals; no allocations) ----
__device__ float g_Wh[BB*NN*FF];                 // 4 MB
__device__ float g_ssrc[BB*NN];
__device__ float g_sdst[BB*NN];
__device__ float g_ysort[BB*NN];
__device__ int   g_perm[BB*NN];
__device__ float g_w1[BB*NN];                    // e^{y} sorted
__device__ float g_wa[BB*NN];                    // e^{alpha y} sorted
__device__ float g_ploc[BB*NN*STR];              // segment-local inclusive scans, k-major ~8.65 MB
__device__ float g_segtot[BB*NSEG*STR];
__device__ float g_segoff[BB*NSEG*STR];
__device__ float g_tot[BB*STR];
__device__ int   g_krank[BB*NN];
__device__ float g_ec[BB*NN];
__device__ float g_eac[BB*NN];

// ============================================================
// K1: Wh = h @ W ; s_src = Wh @ a[:64] ; s_dst = Wh @ a[64:]
// ============================================================
__global__ __launch_bounds__(256) void k_wh(const float* __restrict__ h,
                                            const float* __restrict__ Wm,
                                            const float* __restrict__ av) {
    __shared__ float sW[FF*FF];
    __shared__ float sh[4][FF];
    __shared__ float sred[4][2][2];
    int tid = threadIdx.x;
    for (int i = tid; i < FF*FF; i += 256) sW[i] = Wm[i];
    int r = tid >> 6, f = tid & 63;
    float asrc = av[f], adst = av[FF + f];
    int rowBase = blockIdx.x * 32;

    for (int it = 0; it < 8; ++it) {
        int row = rowBase + it * 4 + r;
        __syncthreads();
        sh[r][f] = h[row*FF + f];
        __syncthreads();
        float acc = 0.f;
        #pragma unroll
        for (int kk = 0; kk < FF; ++kk) acc += sh[r][kk] * sW[kk*FF + f];
        g_Wh[row*FF + f] = acc;
        float ts = acc * asrc, td = acc * adst;
        #pragma unroll
        for (int o = 16; o > 0; o >>= 1) {
            ts += __shfl_down_sync(0xffffffffu, ts, o);
            td += __shfl_down_sync(0xffffffffu, td, o);
        }
        if ((f & 31) == 0) { sred[r][0][f >> 5] = ts; sred[r][1][f >> 5] = td; }
        __syncthreads();
        if (f == 0) {
            g_ssrc[row] = sred[r][0][0] + sred[r][0][1];
            g_sdst[row] = sred[r][1][0] + sred[r][1][1];
        }
    }
}

// ============================================================
// K2: per-batch bitonic sort, 64-bit packed (key-as-sortable-uint | idx)
// Epilogue writes y_sorted, perm, and precomputed e^y, e^{alpha y}.
// ============================================================
__global__ __launch_bounds__(1024) void k_sort() {
    __shared__ unsigned long long s[NN];
    int b = blockIdx.x, tid = threadIdx.x;
    for (int i = tid; i < NN; i += 1024) {
        unsigned u = __float_as_uint(g_sdst[b*NN + i]);
        u = (u & 0x80000000u) ? ~u : (u | 0x80000000u);   // monotone transform
        s[i] = (((unsigned long long)u) << 32) | (unsigned)i;
    }
    for (int size = 2; size <= NN; size <<= 1) {
        bool ddd = ((tid & (size >> 1)) == 0);
        for (int stride = size >> 1; stride > 0; stride >>= 1) {
            __syncthreads();
            int pos = 2*tid - (tid & (stride - 1));
            unsigned long long ka = s[pos], kb = s[pos + stride];
            if ((ka > kb) == ddd) { s[pos] = kb; s[pos + stride] = ka; }
        }
    }
    __syncthreads();
    for (int i = tid; i < NN; i += 1024) {
        unsigned long long v = s[i];
        unsigned t = (unsigned)(v >> 32);
        unsigned u = (t & 0x80000000u) ? (t ^ 0x80000000u) : ~t;
        float y = __uint_as_float(u);
        g_ysort[b*NN + i] = y;
        g_perm [b*NN + i] = (int)(v & 0xFFFFFFFFu);
        g_w1[b*NN + i] = expf(y);
        g_wa[b*NN + i] = expf(ALPHA_ * y);
    }
}

// ============================================================
// K2b: per-row rank (binary search in sorted y) + e^c, e^{alpha c}
// ============================================================
__global__ __launch_bounds__(1024) void k_rank() {
    int b = blockIdx.y;
    int tid = threadIdx.x;
    __shared__ float sy[NN];
    for (int i = tid; i < NN; i += 1024) sy[i] = g_ysort[b*NN + i];
    __syncthreads();
    int row = blockIdx.x * 1024 + tid;
    float c = g_ssrc[b*NN + row];
    float t = -c;
    int lo = 0, hi = NN;                 // first idx with sy[idx] > t
    while (lo < hi) { int mid = (lo + hi) >> 1; if (sy[mid] > t) hi = mid; else lo = mid + 1; }
    g_krank[b*NN + row] = lo;
    g_ec [b*NN + row] = expf(c);
    g_eac[b*NN + row] = expf(ALPHA_ * c);
}

// ============================================================
// K3a: segment-local inclusive scans, k-major layout.
// 64 threads: thread f owns channels f (e^y*Wh) and 64+f (e^{ay}*Wh),
// sharing one coalesced Wh gather per k. Threads 0/1 track scalar channels.
// ============================================================
__global__ __launch_bounds__(64) void k_scanA() {
    int seg = blockIdx.x, b = blockIdx.y, f = threadIdx.x;
    int k0 = seg * SEG;
    __shared__ float sw1[SEG], swa[SEG];
    __shared__ int   spm[SEG];
    sw1[f] = g_w1[b*NN + k0 + f];
    swa[f] = g_wa[b*NN + k0 + f];
    spm[f] = g_perm[b*NN + k0 + f];
    __syncthreads();
    float run1 = 0.f, runa = 0.f, rs1 = 0.f, rsa = 0.f;
    float* P = &g_ploc[(size_t)(b*NN + k0) * STR];
    const float* Whb = &g_Wh[b*NN*FF];
    #pragma unroll 8
    for (int u = 0; u < SEG; ++u) {
        float wh = Whb[spm[u]*FF + f];
        run1 += sw1[u] * wh;
        runa += swa[u] * wh;
        P[u*STR + f]      = run1;
        P[u*STR + 64 + f] = runa;
        if (f == 0) { rs1 += sw1[u]; P[u*STR + 128] = rs1; }
        if (f == 1) { rsa += swa[u]; P[u*STR + 129] = rsa; }
    }
    float* T = &g_segtot[(b*NSEG + seg) * STR];
    T[f] = run1; T[64 + f] = runa;
    if (f == 0) T[128] = rs1;
    if (f == 1) T[129] = rsa;
}

// ============================================================
// K3b: exclusive scan of segment totals + grand totals
// ============================================================
__global__ __launch_bounds__(256) void k_scanB() {
    int b = blockIdx.x, ch = threadIdx.x;
    if (ch >= 130) return;
    float run = 0.f;
    for (int s = 0; s < NSEG; ++s) {
        g_segoff[(b*NSEG + s)*STR + ch] = run;
        run += g_segtot[(b*NSEG + s)*STR + ch];
    }
    g_tot[b*STR + ch] = run;
}

// ============================================================
// K4: output. prefix(k) = segoff[seg(k-1)] + ploc[k-1]; fully coalesced.
// block = 512 thr = 8 rows x 64 f
// ============================================================
__global__ __launch_bounds__(512) void k_out(float* __restrict__ out) {
    int b    = blockIdx.y;
    int row0 = blockIdx.x * 8;
    int tid  = threadIdx.x;
    int r = tid >> 6, f = tid & 63;
    __shared__ float sTot[130];
    __shared__ int   skk[8];
    __shared__ float sec[8], seac[8], sPz[8], sPza[8];
    if (tid < 130) sTot[tid] = g_tot[b*STR + tid];
    if (f == 0) {
        int row = row0 + r;
        int k = g_krank[b*NN + row];
        skk[r]  = k;
        sec[r]  = g_ec [b*NN + row];
        seac[r] = g_eac[b*NN + row];
        if (k > 0) {
            int idx = k - 1, seg = idx >> 6;
            sPz [r] = g_ploc[(size_t)(b*NN + idx)*STR + 128] + g_segoff[(b*NSEG + seg)*STR + 128];
            sPza[r] = g_ploc[(size_t)(b*NN + idx)*STR + 129] + g_segoff[(b*NSEG + seg)*STR + 129];
        } else { sPz[r] = 0.f; sPza[r] = 0.f; }
    }
    __syncthreads();
    int k = skk[r];
    float ec = sec[r], eac = seac[r];
    float P1 = 0.f, Pa = 0.f;
    if (k > 0) {
        int idx = k - 1, seg = idx >> 6;
        const float* Pl = &g_ploc[(size_t)(b*NN + idx)*STR];
        const float* Of = &g_segoff[(b*NSEG + seg)*STR];
        P1 = Pl[f]      + Of[f];
        Pa = Pl[64 + f] + Of[64 + f];
    }
    float num = ec * (sTot[f]   - P1)     + eac * Pa;
    float den = ec * (sTot[128] - sPz[r]) + eac * sPza[r];
    float vv = num / den;
    out[(b*NN + row0 + r)*FF + f] = vv > 0.f ? vv : expm1f(vv);
}

// ============================================================
extern "C" void kernel_launch(void* const* d_in, const int* in_sizes, int n_in,
                              void* d_out, int /*out_size*/) {
    const float *h = nullptr, *Wm = nullptr, *av = nullptr;
    for (int i = 0; i < n_in; ++i) {
        if      (in_sizes[i] == BB*NN*FF) h  = (const float*)d_in[i];
        else if (in_sizes[i] == FF*FF)    Wm = (const float*)d_in[i];
        else if (in_sizes[i] == 2*FF)     av = (const float*)d_in[i];
    }
    k_wh   <<<(BB*NN)/32, 256>>>(h, Wm, av);
    k_sort <<<BB, 1024>>>();
    k_rank <<<dim3(2, BB), 1024>>>();
    k_scanA<<<dim3(NSEG, BB), 64>>>();
    k_scanB<<<BB, 256>>>();
    k_out  <<<dim3(NN/8, BB), 512>>>((float*)d_out);
}

// round 4
// speedup vs baseline: 1.0558x; 1.0558x over previous
#include <cuda_runtime.h>
#include <math.h>

#define BB 8
#define NN 2048
#define FF 64
#define ALPHA_ 0.2f
#define SEG 16
#define SEGSH 4
#define NSEG (NN/SEG)     // 128
#define STR 132           // channel stride: 64 + 64 + 2 scalar + pad

// ---- scratch (static device globals; no allocations) ----
__device__ float g_Wh[BB*NN*FF];                 // 4 MB
__device__ float g_ssrc[BB*NN];
__device__ float g_sdst[BB*NN];
__device__ float g_ysort[BB*NN];
__device__ int   g_perm[BB*NN];
__device__ float g_w1[BB*NN];                    // e^{y} sorted
__device__ float g_wa[BB*NN];                    // e^{alpha y} sorted
__device__ float g_ploc[BB*NN*STR];              // segment-local inclusive scans, k-major ~8.65 MB
__device__ float g_segtot[BB*NSEG*STR];
__device__ float g_segoff[BB*NSEG*STR];
__device__ float g_tot[BB*STR];
__device__ int   g_krank[BB*NN];
__device__ float g_ec[BB*NN];
__device__ float g_eac[BB*NN];

// ============================================================
// K1: Wh = h @ W ; s_src = Wh @ a[:64] ; s_dst = Wh @ a[64:]
// ============================================================
__global__ __launch_bounds__(256) void k_wh(const float* __restrict__ h,
                                            const float* __restrict__ Wm,
                                            const float* __restrict__ av) {
    __shared__ float sW[FF*FF];
    __shared__ float sh[4][FF];
    __shared__ float sred[4][2][2];
    int tid = threadIdx.x;
    for (int i = tid; i < FF*FF; i += 256) sW[i] = Wm[i];
    int r = tid >> 6, f = tid & 63;
    float asrc = av[f], adst = av[FF + f];
    int rowBase = blockIdx.x * 32;

    for (int it = 0; it < 8; ++it) {
        int row = rowBase + it * 4 + r;
        __syncthreads();
        sh[r][f] = h[row*FF + f];
        __syncthreads();
        float acc = 0.f;
        #pragma unroll
        for (int kk = 0; kk < FF; ++kk) acc += sh[r][kk] * sW[kk*FF + f];
        g_Wh[row*FF + f] = acc;
        float ts = acc * asrc, td = acc * adst;
        #pragma unroll
        for (int o = 16; o > 0; o >>= 1) {
            ts += __shfl_down_sync(0xffffffffu, ts, o);
            td += __shfl_down_sync(0xffffffffu, td, o);
        }
        if ((f & 31) == 0) { sred[r][0][f >> 5] = ts; sred[r][1][f >> 5] = td; }
        __syncthreads();
        if (f == 0) {
            g_ssrc[row] = sred[r][0][0] + sred[r][0][1];
            g_sdst[row] = sred[r][1][0] + sred[r][1][1];
        }
    }
}

// ============================================================
// K2: per-batch bitonic sort, 64-bit packed (key-as-sortable-uint | idx)
// ============================================================
__global__ __launch_bounds__(1024) void k_sort() {
    __shared__ unsigned long long s[NN];
    int b = blockIdx.x, tid = threadIdx.x;
    for (int i = tid; i < NN; i += 1024) {
        unsigned u = __float_as_uint(g_sdst[b*NN + i]);
        u = (u & 0x80000000u) ? ~u : (u | 0x80000000u);   // monotone transform
        s[i] = (((unsigned long long)u) << 32) | (unsigned)i;
    }
    for (int size = 2; size <= NN; size <<= 1) {
        bool ddd = ((tid & (size >> 1)) == 0);
        for (int stride = size >> 1; stride > 0; stride >>= 1) {
            __syncthreads();
            int pos = 2*tid - (tid & (stride - 1));
            unsigned long long ka = s[pos], kb = s[pos + stride];
            if ((ka > kb) == ddd) { s[pos] = kb; s[pos + stride] = ka; }
        }
    }
    __syncthreads();
    for (int i = tid; i < NN; i += 1024) {
        unsigned long long v = s[i];
        unsigned t = (unsigned)(v >> 32);
        unsigned u = (t & 0x80000000u) ? (t ^ 0x80000000u) : ~t;
        float y = __uint_as_float(u);
        g_ysort[b*NN + i] = y;
        g_perm [b*NN + i] = (int)(v & 0xFFFFFFFFu);
        g_w1[b*NN + i] = expf(y);
        g_wa[b*NN + i] = expf(ALPHA_ * y);
    }
}

// ============================================================
// K2b: per-row rank (binary search in sorted y) + e^c, e^{alpha c}
// ============================================================
__global__ __launch_bounds__(1024) void k_rank() {
    int b = blockIdx.y;
    int tid = threadIdx.x;
    __shared__ float sy[NN];
    for (int i = tid; i < NN; i += 1024) sy[i] = g_ysort[b*NN + i];
    __syncthreads();
    int row = blockIdx.x * 1024 + tid;
    float c = g_ssrc[b*NN + row];
    float t = -c;
    int lo = 0, hi = NN;                 // first idx with sy[idx] > t
    while (lo < hi) { int mid = (lo + hi) >> 1; if (sy[mid] > t) hi = mid; else lo = mid + 1; }
    g_krank[b*NN + row] = lo;
    g_ec [b*NN + row] = expf(c);
    g_eac[b*NN + row] = expf(ALPHA_ * c);
}

// ============================================================
// K3a: segment-local inclusive scans over SEG=16 keys, k-major layout.
// 1024 blocks x 64 threads -> ~14 warps/SM; short serial chain.
// ============================================================
__global__ __launch_bounds__(64) void k_scanA() {
    int seg = blockIdx.x, b = blockIdx.y, f = threadIdx.x;
    int k0 = seg * SEG;
    __shared__ float sw1[SEG], swa[SEG];
    __shared__ int   spm[SEG];
    if (f < SEG) {
        sw1[f] = g_w1[b*NN + k0 + f];
        swa[f] = g_wa[b*NN + k0 + f];
        spm[f] = g_perm[b*NN + k0 + f];
    }
    __syncthreads();
    float run1 = 0.f, runa = 0.f, rs1 = 0.f, rsa = 0.f;
    float* P = &g_ploc[(size_t)(b*NN + k0) * STR];
    const float* Whb = &g_Wh[b*NN*FF];
    #pragma unroll
    for (int u = 0; u < SEG; ++u) {
        float wh = Whb[spm[u]*FF + f];
        run1 += sw1[u] * wh;
        runa += swa[u] * wh;
        P[u*STR + f]      = run1;
        P[u*STR + 64 + f] = runa;
        if (f == 0) { rs1 += sw1[u]; P[u*STR + 128] = rs1; }
        if (f == 1) { rsa += swa[u]; P[u*STR + 129] = rsa; }
    }
    float* T = &g_segtot[(b*NSEG + seg) * STR];
    T[f] = run1; T[64 + f] = runa;
    if (f == 0) T[128] = rs1;
    if (f == 1) T[129] = rsa;
}

// ============================================================
// K3b: exclusive scan of NSEG=128 segment totals + grand totals.
// Loads coalesced across channel threads; unrolled for MLP.
// ============================================================
__global__ __launch_bounds__(256) void k_scanB() {
    int b = blockIdx.x, ch = threadIdx.x;
    if (ch >= 130) return;
    float run = 0.f;
    #pragma unroll 8
    for (int s = 0; s < NSEG; ++s) {
        float v = g_segtot[(b*NSEG + s)*STR + ch];
        g_segoff[(b*NSEG + s)*STR + ch] = run;
        run += v;
    }
    g_tot[b*STR + ch] = run;
}

// ============================================================
// K4: output. prefix(k) = segoff[seg(k-1)] + ploc[k-1]; coalesced over f.
// ============================================================
__global__ __launch_bounds__(512) void k_out(float* __restrict__ out) {
    int b    = blockIdx.y;
    int row0 = blockIdx.x * 8;
    int tid  = threadIdx.x;
    int r = tid >> 6, f = tid & 63;
    __shared__ float sTot[130];
    __shared__ int   skk[8];
    __shared__ float sec[8], seac[8], sPz[8], sPza[8];
    if (tid < 130) sTot[tid] = g_tot[b*STR + tid];
    if (f == 0) {
        int row = row0 + r;
        int k = g_krank[b*NN + row];
        skk[r]  = k;
        sec[r]  = g_ec [b*NN + row];
        seac[r] = g_eac[b*NN + row];
        if (k > 0) {
            int idx = k - 1, seg = idx >> SEGSH;
            sPz [r] = g_ploc[(size_t)(b*NN + idx)*STR + 128] + g_segoff[(b*NSEG + seg)*STR + 128];
            sPza[r] = g_ploc[(size_t)(b*NN + idx)*STR + 129] + g_segoff[(b*NSEG + seg)*STR + 129];
        } else { sPz[r] = 0.f; sPza[r] = 0.f; }
    }
    __syncthreads();
    int k = skk[r];
    float ec = sec[r], eac = seac[r];
    float P1 = 0.f, Pa = 0.f;
    if (k > 0) {
        int idx = k - 1, seg = idx >> SEGSH;
        const float* Pl = &g_ploc[(size_t)(b*NN + idx)*STR];
        const float* Of = &g_segoff[(b*NSEG + seg)*STR];
        P1 = Pl[f]      + Of[f];
        Pa = Pl[64 + f] + Of[64 + f];
    }
    float num = ec * (sTot[f]   - P1)     + eac * Pa;
    float den = ec * (sTot[128] - sPz[r]) + eac * sPza[r];
    float vv = num / den;
    out[(b*NN + row0 + r)*FF + f] = vv > 0.f ? vv : expm1f(vv);
}

// ============================================================
extern "C" void kernel_launch(void* const* d_in, const int* in_sizes, int n_in,
                              void* d_out, int /*out_size*/) {
    const float *h = nullptr, *Wm = nullptr, *av = nullptr;
    for (int i = 0; i < n_in; ++i) {
        if      (in_sizes[i] == BB*NN*FF) h  = (const float*)d_in[i];
        else if (in_sizes[i] == FF*FF)    Wm = (const float*)d_in[i];
        else if (in_sizes[i] == 2*FF)     av = (const float*)d_in[i];
    }
    k_wh   <<<(BB*NN)/32, 256>>>(h, Wm, av);
    k_sort <<<BB, 1024>>>();
    k_rank <<<dim3(2, BB), 1024>>>();
    k_scanA<<<dim3(NSEG, BB), 64>>>();
    k_scanB<<<BB, 256>>>();
    k_out  <<<dim3(NN/8, BB), 512>>>((float*)d_out);
}